// round 9
// baseline (speedup 1.0000x reference)
#include <cuda_runtime.h>
#include <cuda_bf16.h>
#include <cstdint>

#define NN 50000
#define HH 128
#define CC 16
#define RR 8
#define BB 4
#define EE 800000

// ---------------- scratch (device globals; no allocations) ----------------
__device__ float g_x0[(size_t)NN * HH];              // layer0 out (pre-relu)
__device__ float g_x1[(size_t)NN * HH];              // layer1 out (pre-relu)
__device__ float g_y1[(size_t)4 * NN * HH];          // layer1 basis products Y_b = relu(x0)@B1_b
__device__ float g_z2[(size_t)4 * NN * CC];          // layer2 basis products Z_b = relu(x1)@B2_b
__device__ __nv_bfloat16 g_w1thi[5 * 128 * 128];     // transposed bf16 hi: 0..3 = bases1^T, 4 = loop1^T
__device__ __nv_bfloat16 g_w1tlo[5 * 128 * 128];     // residual lo

// ---------------- helpers ----------------
__device__ __forceinline__ void redAdd4(float* p, float4 v) {
    asm volatile("red.global.add.v4.f32 [%0], {%1, %2, %3, %4};"
                 :: "l"(__cvta_generic_to_global(p)), "f"(v.x), "f"(v.y), "f"(v.z), "f"(v.w)
                 : "memory");
}
__device__ __forceinline__ uint32_t pack_bf16(float a, float b) {
    __nv_bfloat162 t = __floats2bfloat162_rn(a, b);
    return *(uint32_t*)&t;
}
__device__ __forceinline__ uint32_t smem_u32(const void* p) {
    uint32_t a;
    asm("{ .reg .u64 t; cvta.to.shared.u64 t, %1; cvt.u32.u64 %0, t; }" : "=r"(a) : "l"(p));
    return a;
}
#define MMA16816(c, a0, a1, a2, a3, b0, b1)                                   \
    asm volatile("mma.sync.aligned.m16n8k16.row.col.f32.bf16.bf16.f32 "       \
                 "{%0,%1,%2,%3}, {%4,%5,%6,%7}, {%8,%9}, {%0,%1,%2,%3};"      \
                 : "+f"((c)[0]), "+f"((c)[1]), "+f"((c)[2]), "+f"((c)[3])     \
                 : "r"(a0), "r"(a1), "r"(a2), "r"(a3), "r"(b0), "r"(b1))
#define LDSM4(r, addr)                                                        \
    asm volatile("ldmatrix.sync.aligned.m8n8.x4.shared.b16 {%0,%1,%2,%3}, [%4];" \
                 : "=r"((r)[0]), "=r"((r)[1]), "=r"((r)[2]), "=r"((r)[3])     \
                 : "r"(addr))

// smem layout for mma_t128: bf16 rows of stride 136 (128 + 8 pad) halves = 272B
#define LSTRIDE 136
#define AH_OFF 0
#define AL_OFF 34816
#define WH_OFF 69632
#define WL_OFF 104448
#define SMEM_MMA 139264

// ---------------- prep: transpose + bf16 hi/lo split of layer-1 weights ----------------
__global__ void prep_w1t(const float* __restrict__ bases1, const float* __restrict__ loop1,
                         __nv_bfloat16* __restrict__ whi, __nv_bfloat16* __restrict__ wlo) {
    int i = blockIdx.x * 256 + threadIdx.x;
    if (i >= 5 * 16384) return;
    int s = i >> 14;
    int f = (i >> 7) & 127;
    int d = i & 127;
    float v = (s < 4) ? __ldg(&bases1[s * 16384 + d * 128 + f]) : __ldg(&loop1[d * 128 + f]);
    __nv_bfloat16 hi = __float2bfloat16(v);
    __nv_bfloat16 lo = __float2bfloat16(v - __bfloat162float(hi));
    whi[i] = hi;
    wlo[i] = lo;
}

// ---------------- layer 0 init: x0 = loop0[h] + bias0 ----------------
__global__ void init0_k(const int* __restrict__ h, const float* __restrict__ loop0,
                        const float* __restrict__ bias0, float* __restrict__ out) {
    int i = blockIdx.x * 256 + threadIdx.x;
    if (i >= NN * HH) return;
    int n = i >> 7;
    int f = i & 127;
    int id = __ldg(&h[n]);
    out[i] = __ldg(&loop0[(size_t)id * HH + f]) + __ldg(&bias0[f]);
}

// ---------------- layer 0 scatter: one warp per edge, basis-gather ----------------
__global__ void __launch_bounds__(256) scatter0_k(
    const int* __restrict__ src, const int* __restrict__ dst, const int* __restrict__ h,
    const int* __restrict__ rel, const float* __restrict__ norm,
    const float* __restrict__ bases0, const float* __restrict__ wcomp0,
    float* __restrict__ out) {
    int e = (blockIdx.x * 256 + threadIdx.x) >> 5;
    if (e >= EE) return;
    int lane = threadIdx.x & 31;
    int s = __ldg(&src[e]);
    int d = __ldg(&dst[e]);
    int rr = __ldg(&rel[e]);
    float nm = __ldg(&norm[e]);
    int sid = __ldg(&h[s]);
    float c0 = nm * __ldg(&wcomp0[rr * 4 + 0]);
    float c1 = nm * __ldg(&wcomp0[rr * 4 + 1]);
    float c2 = nm * __ldg(&wcomp0[rr * 4 + 2]);
    float c3 = nm * __ldg(&wcomp0[rr * 4 + 3]);
    const float4* bp = (const float4*)bases0;
    const long BS = (long)NN * 32;
    long base = (long)sid * 32 + lane;
    float4 v0 = __ldg(bp + base);
    float4 v1 = __ldg(bp + base + BS);
    float4 v2 = __ldg(bp + base + 2 * BS);
    float4 v3 = __ldg(bp + base + 3 * BS);
    float4 m;
    m.x = c0 * v0.x + c1 * v1.x + c2 * v2.x + c3 * v3.x;
    m.y = c0 * v0.y + c1 * v1.y + c2 * v2.y + c3 * v3.y;
    m.z = c0 * v0.z + c1 * v1.z + c2 * v2.z + c3 * v3.z;
    m.w = c0 * v0.w + c1 * v1.w + c2 * v2.w + c3 * v3.w;
    redAdd4(out + (long)d * HH + lane * 4, m);
}

// ---------------- HMMA transform: out[slice] = relu(x0) @ Wt[slice]^T, bf16 hi/lo split ----------------
// grid = (391, 5): slice<4 -> Y_b; slice==4 -> x1 = . + bias1
// warp tile m32 x n64 (4 M-warps x 2 N-warps), ldmatrix.x4 fragment loads
__global__ void __launch_bounds__(256) mma_t128(
    const float* __restrict__ X,
    const __nv_bfloat16* __restrict__ Wth, const __nv_bfloat16* __restrict__ Wtl,
    float* __restrict__ Y, float* __restrict__ x1, const float* __restrict__ bias1) {
    extern __shared__ char sm[];
    const int tid = threadIdx.x;
    const int w = tid >> 5;
    const int lane = tid & 31;
    const int slice = blockIdx.y;
    const int row0 = blockIdx.x * 128;

    // ---- fill W hi/lo ----
    {
        int r = tid >> 1, half = tid & 1;
        const uint4* gh = (const uint4*)(Wth + slice * 16384) + r * 16 + half * 8;
        const uint4* gl = (const uint4*)(Wtl + slice * 16384) + r * 16 + half * 8;
        uint4* dh = (uint4*)(sm + WH_OFF + r * (LSTRIDE * 2) + half * 128);
        uint4* dl = (uint4*)(sm + WL_OFF + r * (LSTRIDE * 2) + half * 128);
#pragma unroll
        for (int i = 0; i < 8; i++) { dh[i] = __ldg(gh + i); dl[i] = __ldg(gl + i); }
    }
    // ---- fill A: relu(x0) tile, bf16 hi/lo split ----
    {
        int r = tid >> 1, half = tid & 1;
        int rg = row0 + r;
        const float4* xr = (const float4*)X + (long)rg * 32 + half * 16;
        uint32_t* ah = (uint32_t*)(sm + AH_OFF + r * (LSTRIDE * 2) + half * 128);
        uint32_t* al = (uint32_t*)(sm + AL_OFF + r * (LSTRIDE * 2) + half * 128);
#pragma unroll
        for (int i = 0; i < 16; i++) {
            float4 q = (rg < NN) ? __ldg(xr + i) : make_float4(0.f, 0.f, 0.f, 0.f);
            q.x = fmaxf(q.x, 0.f); q.y = fmaxf(q.y, 0.f);
            q.z = fmaxf(q.z, 0.f); q.w = fmaxf(q.w, 0.f);
            float hx = __bfloat162float(__float2bfloat16(q.x));
            float hy = __bfloat162float(__float2bfloat16(q.y));
            float hz = __bfloat162float(__float2bfloat16(q.z));
            float hw = __bfloat162float(__float2bfloat16(q.w));
            ah[i * 2]     = pack_bf16(q.x, q.y);
            ah[i * 2 + 1] = pack_bf16(q.z, q.w);
            al[i * 2]     = pack_bf16(q.x - hx, q.y - hy);
            al[i * 2 + 1] = pack_bf16(q.z - hz, q.w - hw);
        }
    }
    __syncthreads();

    // ---- mainloop: warp (wm, wn) owns rows [32*wm, +32), cols [64*wn, +64) ----
    const int wm = w & 3, wn = w >> 2;
    const int r0 = wm * 32, c0 = wn * 64;
    // ldmatrix per-lane row/khalf offsets (lanes 0-7: tile0, 8-15: tile1, 16-23: tile2, 24-31: tile3)
    const uint32_t lrow = lane & 15;
    const uint32_t lkh = (lane >> 4) << 3;

    const uint32_t sAH = smem_u32(sm + AH_OFF), sAL = smem_u32(sm + AL_OFF);
    const uint32_t sWH = smem_u32(sm + WH_OFF), sWL = smem_u32(sm + WL_OFF);

    float acc[2][8][4];
#pragma unroll
    for (int mi = 0; mi < 2; mi++)
#pragma unroll
        for (int j = 0; j < 8; j++)
            acc[mi][j][0] = acc[mi][j][1] = acc[mi][j][2] = acc[mi][j][3] = 0.f;

#pragma unroll
    for (int ks = 0; ks < 8; ks++) {
        const uint32_t kb = ks * 16 + lkh;
        uint32_t AH[2][4], AL[2][4], BH[4][4], BL[4][4];
#pragma unroll
        for (int mi = 0; mi < 2; mi++) {
            uint32_t off = ((r0 + mi * 16 + lrow) * LSTRIDE + kb) * 2;
            LDSM4(AH[mi], sAH + off);
            LDSM4(AL[mi], sAL + off);
        }
#pragma unroll
        for (int nj = 0; nj < 4; nj++) {
            uint32_t off = ((c0 + nj * 16 + lrow) * LSTRIDE + kb) * 2;
            LDSM4(BH[nj], sWH + off);
            LDSM4(BL[nj], sWL + off);
        }
#pragma unroll
        for (int mi = 0; mi < 2; mi++) {
#pragma unroll
            for (int nj = 0; nj < 4; nj++) {
                float* cA = acc[mi][nj * 2];
                float* cB = acc[mi][nj * 2 + 1];
                MMA16816(cA, AH[mi][0], AH[mi][1], AH[mi][2], AH[mi][3], BH[nj][0], BH[nj][2]);
                MMA16816(cA, AH[mi][0], AH[mi][1], AH[mi][2], AH[mi][3], BL[nj][0], BL[nj][2]);
                MMA16816(cA, AL[mi][0], AL[mi][1], AL[mi][2], AL[mi][3], BH[nj][0], BH[nj][2]);
                MMA16816(cB, AH[mi][0], AH[mi][1], AH[mi][2], AH[mi][3], BH[nj][1], BH[nj][3]);
                MMA16816(cB, AH[mi][0], AH[mi][1], AH[mi][2], AH[mi][3], BL[nj][1], BL[nj][3]);
                MMA16816(cB, AL[mi][0], AL[mi][1], AL[mi][2], AL[mi][3], BH[nj][1], BH[nj][3]);
            }
        }
    }

    // ---- epilogue ----
    float* O = (slice < 4) ? (Y + (long)slice * NN * HH) : x1;
    const int g = lane >> 2, tg = lane & 3;
#pragma unroll
    for (int mi = 0; mi < 2; mi++) {
        long ra = row0 + r0 + mi * 16 + g;
        long rb = ra + 8;
#pragma unroll
        for (int j = 0; j < 8; j++) {
            int col = c0 + j * 8 + tg * 2;
            float b0 = 0.f, b1 = 0.f;
            if (slice == 4) { b0 = __ldg(&bias1[col]); b1 = __ldg(&bias1[col + 1]); }
            if (ra < NN) {
                float2 v = { acc[mi][j][0] + b0, acc[mi][j][1] + b1 };
                *(float2*)(O + ra * 128 + col) = v;
            }
            if (rb < NN) {
                float2 v = { acc[mi][j][2] + b0, acc[mi][j][3] + b1 };
                *(float2*)(O + rb * 128 + col) = v;
            }
        }
    }
}

// ---------------- layer 1 scatter: warp/edge, gather 4 basis rows of Y ----------------
__global__ void __launch_bounds__(256) scatter1_k(
    const int* __restrict__ src, const int* __restrict__ dst, const int* __restrict__ rel,
    const float* __restrict__ norm, const float* __restrict__ wcomp1,
    const float* __restrict__ Y, float* __restrict__ out) {
    int e = (blockIdx.x * 256 + threadIdx.x) >> 5;
    if (e >= EE) return;
    int lane = threadIdx.x & 31;
    int s = __ldg(&src[e]);
    int d = __ldg(&dst[e]);
    int rr = __ldg(&rel[e]);
    float nm = __ldg(&norm[e]);
    float c0 = nm * __ldg(&wcomp1[rr * 4 + 0]);
    float c1 = nm * __ldg(&wcomp1[rr * 4 + 1]);
    float c2 = nm * __ldg(&wcomp1[rr * 4 + 2]);
    float c3 = nm * __ldg(&wcomp1[rr * 4 + 3]);
    const float4* yp = (const float4*)Y;
    const long SS = (long)NN * 32;
    long base = (long)s * 32 + lane;
    float4 v0 = __ldg(yp + base);
    float4 v1 = __ldg(yp + base + SS);
    float4 v2 = __ldg(yp + base + 2 * SS);
    float4 v3 = __ldg(yp + base + 3 * SS);
    float4 m;
    m.x = c0 * v0.x + c1 * v1.x + c2 * v2.x + c3 * v3.x;
    m.y = c0 * v0.y + c1 * v1.y + c2 * v2.y + c3 * v3.y;
    m.z = c0 * v0.z + c1 * v1.z + c2 * v2.z + c3 * v3.z;
    m.w = c0 * v0.w + c1 * v1.w + c2 * v2.w + c3 * v3.w;
    redAdd4(out + (long)d * HH + lane * 4, m);
}

// ---------------- layer 2 transform, F=16: grid.y = 5 (4 bases -> Z, slot 4 -> out+bias) ----------------
__global__ void __launch_bounds__(128) transform16(
    const float* __restrict__ X, const float* __restrict__ bases2,
    const float* __restrict__ loop2, const float* __restrict__ bias2,
    float* __restrict__ Z, float* __restrict__ out) {
    __shared__ float ws[128 * 16];
    __shared__ float xs[64][129];
    const int y = blockIdx.y;
    const float* W = (y < 4) ? (bases2 + y * 2048) : loop2;
    float* O = (y < 4) ? (Z + (long)y * NN * CC) : out;
    const int t = threadIdx.x;
    const int col = t & 15, rg = t >> 4;
    const int row0 = blockIdx.x * 64;
    for (int i = t; i < 128 * 16; i += 128) ws[i] = __ldg(&W[i]);
#pragma unroll 4
    for (int i = 0; i < 64; i++) {
        int rr = row0 + i;
        float v = (rr < NN) ? __ldg(&X[(long)rr * 128 + t]) : 0.f;
        xs[i][t] = fmaxf(v, 0.f);   // relu(x1) fused
    }
    __syncthreads();
    const float bv = (y == 4) ? __ldg(&bias2[col]) : 0.f;
    for (int p = 0; p < 8; p++) {
        int rl = p * 8 + rg;
        float a = 0.f;
#pragma unroll 16
        for (int d = 0; d < 128; d++) a = fmaf(xs[rl][d], ws[d * 16 + col], a);
        int rr = row0 + rl;
        if (rr < NN) O[(long)rr * 16 + col] = a + bv;
    }
}

// ---------------- layer 2 scatter: 4 lanes per edge, gather 4 basis rows of Z ----------------
__global__ void __launch_bounds__(256) scatter2_k(
    const int* __restrict__ src, const int* __restrict__ dst, const int* __restrict__ rel,
    const float* __restrict__ norm, const float* __restrict__ wcomp2,
    const float* __restrict__ Z, float* __restrict__ out) {
    int tid = blockIdx.x * 256 + threadIdx.x;
    int e = tid >> 2;
    if (e >= EE) return;
    int q = tid & 3;
    int s = __ldg(&src[e]);
    int d = __ldg(&dst[e]);
    int rr = __ldg(&rel[e]);
    float nm = __ldg(&norm[e]);
    float c0 = nm * __ldg(&wcomp2[rr * 4 + 0]);
    float c1 = nm * __ldg(&wcomp2[rr * 4 + 1]);
    float c2 = nm * __ldg(&wcomp2[rr * 4 + 2]);
    float c3 = nm * __ldg(&wcomp2[rr * 4 + 3]);
    const float4* zp = (const float4*)Z;
    const long SS = (long)NN * 4;
    long base = (long)s * 4 + q;
    float4 v0 = __ldg(zp + base);
    float4 v1 = __ldg(zp + base + SS);
    float4 v2 = __ldg(zp + base + 2 * SS);
    float4 v3 = __ldg(zp + base + 3 * SS);
    float4 m;
    m.x = c0 * v0.x + c1 * v1.x + c2 * v2.x + c3 * v3.x;
    m.y = c0 * v0.y + c1 * v1.y + c2 * v2.y + c3 * v3.y;
    m.z = c0 * v0.z + c1 * v1.z + c2 * v2.z + c3 * v3.z;
    m.w = c0 * v0.w + c1 * v1.w + c2 * v2.w + c3 * v3.w;
    redAdd4(out + (long)d * CC + q * 4, m);
}

// ---------------- launch ----------------
extern "C" void kernel_launch(void* const* d_in, const int* in_sizes, int n_in,
                              void* d_out, int out_size) {
    const int*   src    = (const int*)d_in[0];
    const int*   dst    = (const int*)d_in[1];
    const int*   h      = (const int*)d_in[2];
    const int*   rtab   = (const int*)d_in[3];
    const float* norm   = (const float*)d_in[4];
    const float* bases0 = (const float*)d_in[5];
    const float* wcomp0 = (const float*)d_in[6];
    const float* loop0  = (const float*)d_in[7];
    const float* bias0  = (const float*)d_in[8];
    const float* bases1 = (const float*)d_in[9];
    const float* wcomp1 = (const float*)d_in[10];
    const float* loop1  = (const float*)d_in[11];
    const float* bias1  = (const float*)d_in[12];
    const float* bases2 = (const float*)d_in[13];
    const float* wcomp2 = (const float*)d_in[14];
    const float* loop2  = (const float*)d_in[15];
    const float* bias2  = (const float*)d_in[16];
    float* out = (float*)d_out;

    float *p_x0, *p_x1, *p_y1, *p_z2;
    __nv_bfloat16 *p_whi, *p_wlo;
    cudaGetSymbolAddress((void**)&p_x0, g_x0);
    cudaGetSymbolAddress((void**)&p_x1, g_x1);
    cudaGetSymbolAddress((void**)&p_y1, g_y1);
    cudaGetSymbolAddress((void**)&p_z2, g_z2);
    cudaGetSymbolAddress((void**)&p_whi, g_w1thi);
    cudaGetSymbolAddress((void**)&p_wlo, g_w1tlo);

    static int attr_done = 0;
    if (!attr_done) {
        cudaFuncSetAttribute(mma_t128, cudaFuncAttributeMaxDynamicSharedMemorySize, SMEM_MMA);
        attr_done = 1;
    }

    const int nh_blocks = (NN * HH + 255) / 256;
    const int edge_warp = (EE * 32 + 255) / 256;
    const int row_t128  = (NN + 127) / 128;   // 391
    const int row_t64   = (NN + 63) / 64;     // 782

    // weight prep (bf16 hi/lo transposed images for HMMA)
    prep_w1t<<<(5 * 16384 + 255) / 256, 256>>>(bases1, loop1, p_whi, p_wlo);

    // ---- layer 0 ----
    init0_k<<<nh_blocks, 256>>>(h, loop0, bias0, p_x0);
    scatter0_k<<<edge_warp, 256>>>(src, dst, h, rtab, norm, bases0, wcomp0, p_x0);

    // ---- layer 1: basis products via HMMA, then basis-gather scatter ----
    mma_t128<<<dim3(row_t128, 5), 256, SMEM_MMA>>>(p_x0, p_whi, p_wlo, p_y1, p_x1, bias1);
    scatter1_k<<<edge_warp, 256>>>(src, dst, rtab, norm, wcomp1, p_y1, p_x1);

    // ---- layer 2 ----
    transform16<<<dim3(row_t64, 5), 128>>>(p_x1, bases2, loop2, bias2, p_z2, out);
    scatter2_k<<<(EE * 4 + 255) / 256, 256>>>(src, dst, rtab, norm, wcomp2, p_z2, out);
}

// round 10
// speedup vs baseline: 1.0391x; 1.0391x over previous
#include <cuda_runtime.h>
#include <cuda_bf16.h>
#include <cstdint>

#define NN 50000
#define HH 128
#define CC 16
#define RR 8
#define BB 4
#define EE 800000

// ---------------- scratch (device globals; no allocations) ----------------
__device__ float g_x0[(size_t)NN * HH];              // layer0 out (pre-relu)
__device__ float g_x1[(size_t)NN * HH];              // layer1 out (pre-relu)
__device__ __nv_bfloat16 g_y1b[(size_t)4 * NN * HH]; // layer1 basis products, bf16 (51.2 MB, L2-resident)
__device__ float g_z2[(size_t)4 * NN * CC];          // layer2 basis products Z_b
__device__ __nv_bfloat16 g_w1thi[5 * 128 * 128];     // transposed bf16 hi: 0..3 = bases1^T, 4 = loop1^T
__device__ __nv_bfloat16 g_w1tlo[5 * 128 * 128];     // residual lo

// ---------------- helpers ----------------
__device__ __forceinline__ void redAdd4(float* p, float4 v) {
    asm volatile("red.global.add.v4.f32 [%0], {%1, %2, %3, %4};"
                 :: "l"(__cvta_generic_to_global(p)), "f"(v.x), "f"(v.y), "f"(v.z), "f"(v.w)
                 : "memory");
}
__device__ __forceinline__ uint32_t pack_bf16(float a, float b) {
    __nv_bfloat162 t = __floats2bfloat162_rn(a, b);
    return *(uint32_t*)&t;
}
__device__ __forceinline__ uint32_t smem_u32(const void* p) {
    uint32_t a;
    asm("{ .reg .u64 t; cvta.to.shared.u64 t, %1; cvt.u32.u64 %0, t; }" : "=r"(a) : "l"(p));
    return a;
}
#define MMA16816(c, a0, a1, a2, a3, b0, b1)                                   \
    asm volatile("mma.sync.aligned.m16n8k16.row.col.f32.bf16.bf16.f32 "       \
                 "{%0,%1,%2,%3}, {%4,%5,%6,%7}, {%8,%9}, {%0,%1,%2,%3};"      \
                 : "+f"((c)[0]), "+f"((c)[1]), "+f"((c)[2]), "+f"((c)[3])     \
                 : "r"(a0), "r"(a1), "r"(a2), "r"(a3), "r"(b0), "r"(b1))
#define LDSM4(r, addr)                                                        \
    asm volatile("ldmatrix.sync.aligned.m8n8.x4.shared.b16 {%0,%1,%2,%3}, [%4];" \
                 : "=r"((r)[0]), "=r"((r)[1]), "=r"((r)[2]), "=r"((r)[3])     \
                 : "r"(addr))

// smem layout: bf16 rows of stride 136 elems (272 B). 64-row A tiles -> 102 KB -> 2 CTAs/SM
#define LSTRIDE 136
#define AH_OFF 0
#define AL_OFF 17408
#define WH_OFF 34816
#define WL_OFF 69632
#define SMEM_MMA 104448

// ---------------- prep: transpose + bf16 hi/lo split of layer-1 weights ----------------
__global__ void prep_w1t(const float* __restrict__ bases1, const float* __restrict__ loop1,
                         __nv_bfloat16* __restrict__ whi, __nv_bfloat16* __restrict__ wlo) {
    int i = blockIdx.x * 256 + threadIdx.x;
    if (i >= 5 * 16384) return;
    int s = i >> 14;
    int f = (i >> 7) & 127;
    int d = i & 127;
    float v = (s < 4) ? __ldg(&bases1[s * 16384 + d * 128 + f]) : __ldg(&loop1[d * 128 + f]);
    __nv_bfloat16 hi = __float2bfloat16(v);
    __nv_bfloat16 lo = __float2bfloat16(v - __bfloat162float(hi));
    whi[i] = hi;
    wlo[i] = lo;
}

// ---------------- layer 0 init: x0 = loop0[h] + bias0 ----------------
__global__ void init0_k(const int* __restrict__ h, const float* __restrict__ loop0,
                        const float* __restrict__ bias0, float* __restrict__ out) {
    int i = blockIdx.x * 256 + threadIdx.x;
    if (i >= NN * HH) return;
    int n = i >> 7;
    int f = i & 127;
    int id = __ldg(&h[n]);
    out[i] = __ldg(&loop0[(size_t)id * HH + f]) + __ldg(&bias0[f]);
}

// ---------------- layer 0 scatter: one warp per edge, basis-gather ----------------
__global__ void __launch_bounds__(256) scatter0_k(
    const int* __restrict__ src, const int* __restrict__ dst, const int* __restrict__ h,
    const int* __restrict__ rel, const float* __restrict__ norm,
    const float* __restrict__ bases0, const float* __restrict__ wcomp0,
    float* __restrict__ out) {
    int e = (blockIdx.x * 256 + threadIdx.x) >> 5;
    if (e >= EE) return;
    int lane = threadIdx.x & 31;
    int s = __ldg(&src[e]);
    int d = __ldg(&dst[e]);
    int rr = __ldg(&rel[e]);
    float nm = __ldg(&norm[e]);
    int sid = __ldg(&h[s]);
    float c0 = nm * __ldg(&wcomp0[rr * 4 + 0]);
    float c1 = nm * __ldg(&wcomp0[rr * 4 + 1]);
    float c2 = nm * __ldg(&wcomp0[rr * 4 + 2]);
    float c3 = nm * __ldg(&wcomp0[rr * 4 + 3]);
    const float4* bp = (const float4*)bases0;
    const long BS = (long)NN * 32;
    long base = (long)sid * 32 + lane;
    float4 v0 = __ldg(bp + base);
    float4 v1 = __ldg(bp + base + BS);
    float4 v2 = __ldg(bp + base + 2 * BS);
    float4 v3 = __ldg(bp + base + 3 * BS);
    float4 m;
    m.x = c0 * v0.x + c1 * v1.x + c2 * v2.x + c3 * v3.x;
    m.y = c0 * v0.y + c1 * v1.y + c2 * v2.y + c3 * v3.y;
    m.z = c0 * v0.z + c1 * v1.z + c2 * v2.z + c3 * v3.z;
    m.w = c0 * v0.w + c1 * v1.w + c2 * v2.w + c3 * v3.w;
    redAdd4(out + (long)d * HH + lane * 4, m);
}

// ---------------- HMMA transform: 64-row tiles, 2 CTAs/SM ----------------
// grid = (782, 5): slice<4 -> Yb (bf16); slice==4 -> x1 = . + bias1 (fp32)
// warp tile m32 x n32 (2 M-warps x 4 N-warps), ldmatrix.x4 fragment loads
__global__ void __launch_bounds__(256, 2) mma_t128(
    const float* __restrict__ X,
    const __nv_bfloat16* __restrict__ Wth, const __nv_bfloat16* __restrict__ Wtl,
    __nv_bfloat16* __restrict__ Yb, float* __restrict__ x1, const float* __restrict__ bias1) {
    extern __shared__ char sm[];
    const int tid = threadIdx.x;
    const int w = tid >> 5;
    const int lane = tid & 31;
    const int slice = blockIdx.y;
    const int row0 = blockIdx.x * 64;

    // ---- fill W hi/lo (128 rows x 256B each) ----
    {
        int r = tid >> 1, half = tid & 1;
        const uint4* gh = (const uint4*)(Wth + slice * 16384) + r * 16 + half * 8;
        const uint4* gl = (const uint4*)(Wtl + slice * 16384) + r * 16 + half * 8;
        uint4* dh = (uint4*)(sm + WH_OFF + r * (LSTRIDE * 2) + half * 128);
        uint4* dl = (uint4*)(sm + WL_OFF + r * (LSTRIDE * 2) + half * 128);
#pragma unroll
        for (int i = 0; i < 8; i++) { dh[i] = __ldg(gh + i); dl[i] = __ldg(gl + i); }
    }
    // ---- fill A: 64 rows of relu(X), bf16 hi/lo split ----
    {
        int r = tid & 63, seg = tid >> 6;           // seg covers cols [32*seg, +32)
        int rg = row0 + r;
        const float4* xr = (const float4*)X + (long)rg * 32 + seg * 8;
        uint32_t* ah = (uint32_t*)(sm + AH_OFF + r * (LSTRIDE * 2) + seg * 64);
        uint32_t* al = (uint32_t*)(sm + AL_OFF + r * (LSTRIDE * 2) + seg * 64);
#pragma unroll
        for (int i = 0; i < 8; i++) {
            float4 q = (rg < NN) ? __ldg(xr + i) : make_float4(0.f, 0.f, 0.f, 0.f);
            q.x = fmaxf(q.x, 0.f); q.y = fmaxf(q.y, 0.f);
            q.z = fmaxf(q.z, 0.f); q.w = fmaxf(q.w, 0.f);
            float hx = __bfloat162float(__float2bfloat16(q.x));
            float hy = __bfloat162float(__float2bfloat16(q.y));
            float hz = __bfloat162float(__float2bfloat16(q.z));
            float hw = __bfloat162float(__float2bfloat16(q.w));
            ah[i * 2]     = pack_bf16(q.x, q.y);
            ah[i * 2 + 1] = pack_bf16(q.z, q.w);
            al[i * 2]     = pack_bf16(q.x - hx, q.y - hy);
            al[i * 2 + 1] = pack_bf16(q.z - hz, q.w - hw);
        }
    }
    __syncthreads();

    // ---- mainloop: warp (wm, wn) owns rows [32*wm, +32), cols [32*wn, +32) ----
    const int wm = w & 1, wn = w >> 1;
    const int r0 = wm * 32, c0 = wn * 32;
    const uint32_t lrow = lane & 15;
    const uint32_t lkh = (lane >> 4) << 3;

    const uint32_t sAH = smem_u32(sm + AH_OFF), sAL = smem_u32(sm + AL_OFF);
    const uint32_t sWH = smem_u32(sm + WH_OFF), sWL = smem_u32(sm + WL_OFF);

    float acc[2][4][4];
#pragma unroll
    for (int mi = 0; mi < 2; mi++)
#pragma unroll
        for (int j = 0; j < 4; j++)
            acc[mi][j][0] = acc[mi][j][1] = acc[mi][j][2] = acc[mi][j][3] = 0.f;

#pragma unroll
    for (int ks = 0; ks < 8; ks++) {
        const uint32_t kb = ks * 16 + lkh;
        uint32_t AH[2][4], AL[2][4], BH[2][4], BL[2][4];
#pragma unroll
        for (int mi = 0; mi < 2; mi++) {
            uint32_t off = ((r0 + mi * 16 + lrow) * LSTRIDE + kb) * 2;
            LDSM4(AH[mi], sAH + off);
            LDSM4(AL[mi], sAL + off);
        }
#pragma unroll
        for (int nj = 0; nj < 2; nj++) {
            uint32_t off = ((c0 + nj * 16 + lrow) * LSTRIDE + kb) * 2;
            LDSM4(BH[nj], sWH + off);
            LDSM4(BL[nj], sWL + off);
        }
#pragma unroll
        for (int mi = 0; mi < 2; mi++) {
#pragma unroll
            for (int nj = 0; nj < 2; nj++) {
                float* cA = acc[mi][nj * 2];
                float* cB = acc[mi][nj * 2 + 1];
                MMA16816(cA, AH[mi][0], AH[mi][1], AH[mi][2], AH[mi][3], BH[nj][0], BH[nj][2]);
                MMA16816(cA, AH[mi][0], AH[mi][1], AH[mi][2], AH[mi][3], BL[nj][0], BL[nj][2]);
                MMA16816(cA, AL[mi][0], AL[mi][1], AL[mi][2], AL[mi][3], BH[nj][0], BH[nj][2]);
                MMA16816(cB, AH[mi][0], AH[mi][1], AH[mi][2], AH[mi][3], BH[nj][1], BH[nj][3]);
                MMA16816(cB, AH[mi][0], AH[mi][1], AH[mi][2], AH[mi][3], BL[nj][1], BL[nj][3]);
                MMA16816(cB, AL[mi][0], AL[mi][1], AL[mi][2], AL[mi][3], BH[nj][1], BH[nj][3]);
            }
        }
    }

    // ---- epilogue ----
    const int g = lane >> 2, tg = lane & 3;
    if (slice < 4) {
        __nv_bfloat16* O = Yb + (size_t)slice * NN * HH;
#pragma unroll
        for (int mi = 0; mi < 2; mi++) {
            long ra = row0 + r0 + mi * 16 + g;
            long rb = ra + 8;
#pragma unroll
            for (int j = 0; j < 4; j++) {
                int col = c0 + j * 8 + tg * 2;
                if (ra < NN) *(uint32_t*)(O + ra * 128 + col) = pack_bf16(acc[mi][j][0], acc[mi][j][1]);
                if (rb < NN) *(uint32_t*)(O + rb * 128 + col) = pack_bf16(acc[mi][j][2], acc[mi][j][3]);
            }
        }
    } else {
#pragma unroll
        for (int mi = 0; mi < 2; mi++) {
            long ra = row0 + r0 + mi * 16 + g;
            long rb = ra + 8;
#pragma unroll
            for (int j = 0; j < 4; j++) {
                int col = c0 + j * 8 + tg * 2;
                float b0 = __ldg(&bias1[col]), b1 = __ldg(&bias1[col + 1]);
                if (ra < NN) {
                    float2 v = { acc[mi][j][0] + b0, acc[mi][j][1] + b1 };
                    *(float2*)(x1 + ra * 128 + col) = v;
                }
                if (rb < NN) {
                    float2 v = { acc[mi][j][2] + b0, acc[mi][j][3] + b1 };
                    *(float2*)(x1 + rb * 128 + col) = v;
                }
            }
        }
    }
}

// ---------------- layer 1 scatter: warp/edge, gather 4 bf16 basis rows of Y ----------------
__global__ void __launch_bounds__(256) scatter1_k(
    const int* __restrict__ src, const int* __restrict__ dst, const int* __restrict__ rel,
    const float* __restrict__ norm, const float* __restrict__ wcomp1,
    const __nv_bfloat16* __restrict__ Yb, float* __restrict__ out) {
    int e = (blockIdx.x * 256 + threadIdx.x) >> 5;
    if (e >= EE) return;
    int lane = threadIdx.x & 31;
    int s = __ldg(&src[e]);
    int d = __ldg(&dst[e]);
    int rr = __ldg(&rel[e]);
    float nm = __ldg(&norm[e]);
    float c0 = nm * __ldg(&wcomp1[rr * 4 + 0]);
    float c1 = nm * __ldg(&wcomp1[rr * 4 + 1]);
    float c2 = nm * __ldg(&wcomp1[rr * 4 + 2]);
    float c3 = nm * __ldg(&wcomp1[rr * 4 + 3]);
    // lane covers cols [lane*4, +4): 4 bf16 = uint2 per basis
    const uint2* yp = (const uint2*)Yb + (long)s * 32 + lane;   // 128 bf16 = 32 uint2 per row
    const long SS = (long)NN * 32;
    uint2 u0 = __ldg(yp);
    uint2 u1 = __ldg(yp + SS);
    uint2 u2 = __ldg(yp + 2 * SS);
    uint2 u3 = __ldg(yp + 3 * SS);
    float2 a0 = __bfloat1622float2(*(const __nv_bfloat162*)&u0.x);
    float2 b0 = __bfloat1622float2(*(const __nv_bfloat162*)&u0.y);
    float2 a1 = __bfloat1622float2(*(const __nv_bfloat162*)&u1.x);
    float2 b1 = __bfloat1622float2(*(const __nv_bfloat162*)&u1.y);
    float2 a2 = __bfloat1622float2(*(const __nv_bfloat162*)&u2.x);
    float2 b2 = __bfloat1622float2(*(const __nv_bfloat162*)&u2.y);
    float2 a3 = __bfloat1622float2(*(const __nv_bfloat162*)&u3.x);
    float2 b3 = __bfloat1622float2(*(const __nv_bfloat162*)&u3.y);
    float4 m;
    m.x = c0 * a0.x + c1 * a1.x + c2 * a2.x + c3 * a3.x;
    m.y = c0 * a0.y + c1 * a1.y + c2 * a2.y + c3 * a3.y;
    m.z = c0 * b0.x + c1 * b1.x + c2 * b2.x + c3 * b3.x;
    m.w = c0 * b0.y + c1 * b1.y + c2 * b2.y + c3 * b3.y;
    redAdd4(out + (long)d * HH + lane * 4, m);
}

// ---------------- layer 2 transform, F=16: grid.y = 5 (4 bases -> Z, slot 4 -> out+bias) ----------------
__global__ void __launch_bounds__(128) transform16(
    const float* __restrict__ X, const float* __restrict__ bases2,
    const float* __restrict__ loop2, const float* __restrict__ bias2,
    float* __restrict__ Z, float* __restrict__ out) {
    __shared__ float ws[128 * 16];
    __shared__ float xs[64][129];
    const int y = blockIdx.y;
    const float* W = (y < 4) ? (bases2 + y * 2048) : loop2;
    float* O = (y < 4) ? (Z + (long)y * NN * CC) : out;
    const int t = threadIdx.x;
    const int col = t & 15, rg = t >> 4;
    const int row0 = blockIdx.x * 64;
    for (int i = t; i < 128 * 16; i += 128) ws[i] = __ldg(&W[i]);
#pragma unroll 4
    for (int i = 0; i < 64; i++) {
        int rr = row0 + i;
        float v = (rr < NN) ? __ldg(&X[(long)rr * 128 + t]) : 0.f;
        xs[i][t] = fmaxf(v, 0.f);   // relu(x1) fused
    }
    __syncthreads();
    const float bv = (y == 4) ? __ldg(&bias2[col]) : 0.f;
    for (int p = 0; p < 8; p++) {
        int rl = p * 8 + rg;
        float a = 0.f;
#pragma unroll 16
        for (int d = 0; d < 128; d++) a = fmaf(xs[rl][d], ws[d * 16 + col], a);
        int rr = row0 + rl;
        if (rr < NN) O[(long)rr * 16 + col] = a + bv;
    }
}

// ---------------- layer 2 scatter: 4 lanes per edge, gather 4 basis rows of Z ----------------
__global__ void __launch_bounds__(256) scatter2_k(
    const int* __restrict__ src, const int* __restrict__ dst, const int* __restrict__ rel,
    const float* __restrict__ norm, const float* __restrict__ wcomp2,
    const float* __restrict__ Z, float* __restrict__ out) {
    int tid = blockIdx.x * 256 + threadIdx.x;
    int e = tid >> 2;
    if (e >= EE) return;
    int q = tid & 3;
    int s = __ldg(&src[e]);
    int d = __ldg(&dst[e]);
    int rr = __ldg(&rel[e]);
    float nm = __ldg(&norm[e]);
    float c0 = nm * __ldg(&wcomp2[rr * 4 + 0]);
    float c1 = nm * __ldg(&wcomp2[rr * 4 + 1]);
    float c2 = nm * __ldg(&wcomp2[rr * 4 + 2]);
    float c3 = nm * __ldg(&wcomp2[rr * 4 + 3]);
    const float4* zp = (const float4*)Z;
    const long SS = (long)NN * 4;
    long base = (long)s * 4 + q;
    float4 v0 = __ldg(zp + base);
    float4 v1 = __ldg(zp + base + SS);
    float4 v2 = __ldg(zp + base + 2 * SS);
    float4 v3 = __ldg(zp + base + 3 * SS);
    float4 m;
    m.x = c0 * v0.x + c1 * v1.x + c2 * v2.x + c3 * v3.x;
    m.y = c0 * v0.y + c1 * v1.y + c2 * v2.y + c3 * v3.y;
    m.z = c0 * v0.z + c1 * v1.z + c2 * v2.z + c3 * v3.z;
    m.w = c0 * v0.w + c1 * v1.w + c2 * v2.w + c3 * v3.w;
    redAdd4(out + (long)d * CC + q * 4, m);
}

// ---------------- launch ----------------
extern "C" void kernel_launch(void* const* d_in, const int* in_sizes, int n_in,
                              void* d_out, int out_size) {
    const int*   src    = (const int*)d_in[0];
    const int*   dst    = (const int*)d_in[1];
    const int*   h      = (const int*)d_in[2];
    const int*   rtab   = (const int*)d_in[3];
    const float* norm   = (const float*)d_in[4];
    const float* bases0 = (const float*)d_in[5];
    const float* wcomp0 = (const float*)d_in[6];
    const float* loop0  = (const float*)d_in[7];
    const float* bias0  = (const float*)d_in[8];
    const float* bases1 = (const float*)d_in[9];
    const float* wcomp1 = (const float*)d_in[10];
    const float* loop1  = (const float*)d_in[11];
    const float* bias1  = (const float*)d_in[12];
    const float* bases2 = (const float*)d_in[13];
    const float* wcomp2 = (const float*)d_in[14];
    const float* loop2  = (const float*)d_in[15];
    const float* bias2  = (const float*)d_in[16];
    float* out = (float*)d_out;

    float *p_x0, *p_x1, *p_z2;
    __nv_bfloat16 *p_y1b, *p_whi, *p_wlo;
    cudaGetSymbolAddress((void**)&p_x0, g_x0);
    cudaGetSymbolAddress((void**)&p_x1, g_x1);
    cudaGetSymbolAddress((void**)&p_y1b, g_y1b);
    cudaGetSymbolAddress((void**)&p_z2, g_z2);
    cudaGetSymbolAddress((void**)&p_whi, g_w1thi);
    cudaGetSymbolAddress((void**)&p_wlo, g_w1tlo);

    static int attr_done = 0;
    if (!attr_done) {
        cudaFuncSetAttribute(mma_t128, cudaFuncAttributeMaxDynamicSharedMemorySize, SMEM_MMA);
        attr_done = 1;
    }

    const int nh_blocks = (NN * HH + 255) / 256;
    const int edge_warp = (EE * 32 + 255) / 256;
    const int row_t64m = (NN + 63) / 64;     // 782 (mma tiles)
    const int row_t64  = (NN + 63) / 64;     // 782 (transform16 tiles)

    // weight prep (bf16 hi/lo transposed images for HMMA)
    prep_w1t<<<(5 * 16384 + 255) / 256, 256>>>(bases1, loop1, p_whi, p_wlo);

    // ---- layer 0 ----
    init0_k<<<nh_blocks, 256>>>(h, loop0, bias0, p_x0);
    scatter0_k<<<edge_warp, 256>>>(src, dst, h, rtab, norm, bases0, wcomp0, p_x0);

    // ---- layer 1: basis products via HMMA (bf16 Y), then basis-gather scatter ----
    mma_t128<<<dim3(row_t64m, 5), 256, SMEM_MMA>>>(p_x0, p_whi, p_wlo, p_y1b, p_x1, bias1);
    scatter1_k<<<edge_warp, 256>>>(src, dst, rtab, norm, wcomp1, p_y1b, p_x1);

    // ---- layer 2 ----
    transform16<<<dim3(row_t64, 5), 128>>>(p_x1, bases2, loop2, bias2, p_z2, out);
    scatter2_k<<<(EE * 4 + 255) / 256, 256>>>(src, dst, rtab, norm, wcomp2, p_z2, out);
}

// round 11
// speedup vs baseline: 1.2470x; 1.2000x over previous
#include <cuda_runtime.h>
#include <cuda_bf16.h>
#include <cuda_fp16.h>
#include <cstdint>

#define NN 50000
#define HH 128
#define CC 16
#define RR 8
#define BB 4
#define EE 800000

// ---------------- scratch (device globals; no allocations) ----------------
__device__ float g_x0[(size_t)NN * HH];              // layer0 out (pre-relu)
__device__ float g_x1[(size_t)NN * HH];              // layer1 out (pre-relu)
__device__ __half g_b0h[(size_t)BB * NN * HH];       // fp16 copy of bases0 (51.2 MB, L2-resident)
__device__ __half g_y1h[(size_t)4 * NN * HH];        // layer1 basis products, fp16 (51.2 MB)
__device__ float g_z2[(size_t)4 * NN * CC];          // layer2 basis products Z_b
__device__ __nv_bfloat16 g_w1thi[5 * 128 * 128];     // transposed bf16 hi: 0..3 = bases1^T, 4 = loop1^T
__device__ __nv_bfloat16 g_w1tlo[5 * 128 * 128];     // residual lo

// ---------------- helpers ----------------
__device__ __forceinline__ void redAdd4(float* p, float4 v) {
    asm volatile("red.global.add.v4.f32 [%0], {%1, %2, %3, %4};"
                 :: "l"(__cvta_generic_to_global(p)), "f"(v.x), "f"(v.y), "f"(v.z), "f"(v.w)
                 : "memory");
}
__device__ __forceinline__ uint32_t pack_bf16(float a, float b) {
    __nv_bfloat162 t = __floats2bfloat162_rn(a, b);
    return *(uint32_t*)&t;
}
__device__ __forceinline__ uint32_t pack_f16(float a, float b) {
    __half2 t = __floats2half2_rn(a, b);
    return *(uint32_t*)&t;
}
__device__ __forceinline__ uint32_t smem_u32(const void* p) {
    uint32_t a;
    asm("{ .reg .u64 t; cvta.to.shared.u64 t, %1; cvt.u32.u64 %0, t; }" : "=r"(a) : "l"(p));
    return a;
}
#define MMA16816(c, a0, a1, a2, a3, b0, b1)                                   \
    asm volatile("mma.sync.aligned.m16n8k16.row.col.f32.bf16.bf16.f32 "       \
                 "{%0,%1,%2,%3}, {%4,%5,%6,%7}, {%8,%9}, {%0,%1,%2,%3};"      \
                 : "+f"((c)[0]), "+f"((c)[1]), "+f"((c)[2]), "+f"((c)[3])     \
                 : "r"(a0), "r"(a1), "r"(a2), "r"(a3), "r"(b0), "r"(b1))
#define LDSM4(r, addr)                                                        \
    asm volatile("ldmatrix.sync.aligned.m8n8.x4.shared.b16 {%0,%1,%2,%3}, [%4];" \
                 : "=r"((r)[0]), "=r"((r)[1]), "=r"((r)[2]), "=r"((r)[3])     \
                 : "r"(addr))

// smem: bf16 rows, stride 136 elems (272 B). A 64 rows + W 128 rows, hi/lo -> 102 KB -> 2 CTAs/SM
#define LSTRIDE 136
#define AH_OFF 0
#define AL_OFF 17408
#define WH_OFF 34816
#define WL_OFF 69632
#define SMEM_MMA 104448

// ---------------- prep: transpose + bf16 hi/lo split of layer-1 weights ----------------
__global__ void prep_w1t(const float* __restrict__ bases1, const float* __restrict__ loop1,
                         __nv_bfloat16* __restrict__ whi, __nv_bfloat16* __restrict__ wlo) {
    int i = blockIdx.x * 256 + threadIdx.x;
    if (i >= 5 * 16384) return;
    int s = i >> 14;
    int f = (i >> 7) & 127;
    int d = i & 127;
    float v = (s < 4) ? __ldg(&bases1[s * 16384 + d * 128 + f]) : __ldg(&loop1[d * 128 + f]);
    __nv_bfloat16 hi = __float2bfloat16(v);
    __nv_bfloat16 lo = __float2bfloat16(v - __bfloat162float(hi));
    whi[i] = hi;
    wlo[i] = lo;
}

// ---------------- prep: bases0 fp32 -> fp16 (streaming, vectorized) ----------------
__global__ void cvt_b0h(const float* __restrict__ b0, __half* __restrict__ out) {
    int i = blockIdx.x * 256 + threadIdx.x;          // over float4 groups
    if (i >= BB * NN * 32) return;
    float4 v = __ldg((const float4*)b0 + i);
    __half2 h0 = __floats2half2_rn(v.x, v.y);
    __half2 h1 = __floats2half2_rn(v.z, v.w);
    uint2 u = { *(uint32_t*)&h0, *(uint32_t*)&h1 };
    ((uint2*)out)[i] = u;
}

// ---------------- layer 0 init: x0 = loop0[h] + bias0 ----------------
__global__ void init0_k(const int* __restrict__ h, const float* __restrict__ loop0,
                        const float* __restrict__ bias0, float* __restrict__ out) {
    int i = blockIdx.x * 256 + threadIdx.x;
    if (i >= NN * HH) return;
    int n = i >> 7;
    int f = i & 127;
    int id = __ldg(&h[n]);
    out[i] = __ldg(&loop0[(size_t)id * HH + f]) + __ldg(&bias0[f]);
}

// ---------------- layer 0 scatter: one warp per edge, fp16 basis-gather ----------------
__global__ void __launch_bounds__(256) scatter0_k(
    const int* __restrict__ src, const int* __restrict__ dst, const int* __restrict__ h,
    const int* __restrict__ rel, const float* __restrict__ norm,
    const __half* __restrict__ b0h, const float* __restrict__ wcomp0,
    float* __restrict__ out) {
    int e = (blockIdx.x * 256 + threadIdx.x) >> 5;
    if (e >= EE) return;
    int lane = threadIdx.x & 31;
    int s = __ldg(&src[e]);
    int d = __ldg(&dst[e]);
    int rr = __ldg(&rel[e]);
    float nm = __ldg(&norm[e]);
    int sid = __ldg(&h[s]);
    float c0 = nm * __ldg(&wcomp0[rr * 4 + 0]);
    float c1 = nm * __ldg(&wcomp0[rr * 4 + 1]);
    float c2 = nm * __ldg(&wcomp0[rr * 4 + 2]);
    float c3 = nm * __ldg(&wcomp0[rr * 4 + 3]);
    const uint2* bp = (const uint2*)b0h;             // row = 32 uint2 (128 fp16)
    const long BS = (long)NN * 32;
    long base = (long)sid * 32 + lane;
    uint2 u0 = __ldg(bp + base);
    uint2 u1 = __ldg(bp + base + BS);
    uint2 u2 = __ldg(bp + base + 2 * BS);
    uint2 u3 = __ldg(bp + base + 3 * BS);
    float2 a0 = __half22float2(*(const __half2*)&u0.x), b0 = __half22float2(*(const __half2*)&u0.y);
    float2 a1 = __half22float2(*(const __half2*)&u1.x), b1 = __half22float2(*(const __half2*)&u1.y);
    float2 a2 = __half22float2(*(const __half2*)&u2.x), b2 = __half22float2(*(const __half2*)&u2.y);
    float2 a3 = __half22float2(*(const __half2*)&u3.x), b3 = __half22float2(*(const __half2*)&u3.y);
    float4 m;
    m.x = c0 * a0.x + c1 * a1.x + c2 * a2.x + c3 * a3.x;
    m.y = c0 * a0.y + c1 * a1.y + c2 * a2.y + c3 * a3.y;
    m.z = c0 * b0.x + c1 * b1.x + c2 * b2.x + c3 * b3.x;
    m.w = c0 * b0.y + c1 * b1.y + c2 * b2.y + c3 * b3.y;
    redAdd4(out + (long)d * HH + lane * 4, m);
}

// ---------------- HMMA transform: 64-row tiles, 2 CTAs/SM, conflict-free fills ----------------
// grid = (782, 5): slice<4 -> Yh (fp16); slice==4 -> x1 = . + bias1 (fp32)
__global__ void __launch_bounds__(256, 2) mma_t128(
    const float* __restrict__ X,
    const __nv_bfloat16* __restrict__ Wth, const __nv_bfloat16* __restrict__ Wtl,
    __half* __restrict__ Yh, float* __restrict__ x1, const float* __restrict__ bias1) {
    extern __shared__ char sm[];
    const int tid = threadIdx.x;
    const int w = tid >> 5;
    const int lane = tid & 31;
    const int slice = blockIdx.y;
    const int row0 = blockIdx.x * 64;

    // ---- fill W hi/lo: warp w -> rows [16w, 16w+16), lane -> 8B chunk (coalesced LDG, ~CF STS.64) ----
    {
        const uint2* gh = (const uint2*)(Wth + slice * 16384);
        const uint2* gl = (const uint2*)(Wtl + slice * 16384);
#pragma unroll
        for (int i = 0; i < 16; i++) {
            int r = w * 16 + i;
            uint2 vh = __ldg(gh + r * 32 + lane);
            uint2 vl = __ldg(gl + r * 32 + lane);
            *(uint2*)(sm + WH_OFF + r * (LSTRIDE * 2) + lane * 8) = vh;
            *(uint2*)(sm + WL_OFF + r * (LSTRIDE * 2) + lane * 8) = vl;
        }
    }
    // ---- fill A: warp w -> rows [8w, 8w+8), lane -> 4 cols (coalesced float4 LDG) ----
    {
#pragma unroll
        for (int i = 0; i < 8; i++) {
            int r = w * 8 + i;
            int rg = row0 + r;
            float4 q = (rg < NN) ? __ldg((const float4*)X + (long)rg * 32 + lane)
                                 : make_float4(0.f, 0.f, 0.f, 0.f);
            q.x = fmaxf(q.x, 0.f); q.y = fmaxf(q.y, 0.f);
            q.z = fmaxf(q.z, 0.f); q.w = fmaxf(q.w, 0.f);
            float hx = __bfloat162float(__float2bfloat16(q.x));
            float hy = __bfloat162float(__float2bfloat16(q.y));
            float hz = __bfloat162float(__float2bfloat16(q.z));
            float hw = __bfloat162float(__float2bfloat16(q.w));
            uint2 uh = { pack_bf16(q.x, q.y), pack_bf16(q.z, q.w) };
            uint2 ul = { pack_bf16(q.x - hx, q.y - hy), pack_bf16(q.z - hz, q.w - hw) };
            *(uint2*)(sm + AH_OFF + r * (LSTRIDE * 2) + lane * 8) = uh;
            *(uint2*)(sm + AL_OFF + r * (LSTRIDE * 2) + lane * 8) = ul;
        }
    }
    __syncthreads();

    // ---- mainloop: warp (wm, wn) owns rows [32*wm, +32), cols [32*wn, +32) ----
    const int wm = w & 1, wn = w >> 1;
    const int r0 = wm * 32, c0 = wn * 32;
    const uint32_t lrow = lane & 15;
    const uint32_t lkh = (lane >> 4) << 3;

    const uint32_t sAH = smem_u32(sm + AH_OFF), sAL = smem_u32(sm + AL_OFF);
    const uint32_t sWH = smem_u32(sm + WH_OFF), sWL = smem_u32(sm + WL_OFF);

    float acc[2][4][4];
#pragma unroll
    for (int mi = 0; mi < 2; mi++)
#pragma unroll
        for (int j = 0; j < 4; j++)
            acc[mi][j][0] = acc[mi][j][1] = acc[mi][j][2] = acc[mi][j][3] = 0.f;

#pragma unroll
    for (int ks = 0; ks < 8; ks++) {
        const uint32_t kb = ks * 16 + lkh;
        uint32_t AH[2][4], AL[2][4], BH[2][4], BL[2][4];
#pragma unroll
        for (int mi = 0; mi < 2; mi++) {
            uint32_t off = ((r0 + mi * 16 + lrow) * LSTRIDE + kb) * 2;
            LDSM4(AH[mi], sAH + off);
            LDSM4(AL[mi], sAL + off);
        }
#pragma unroll
        for (int nj = 0; nj < 2; nj++) {
            uint32_t off = ((c0 + nj * 16 + lrow) * LSTRIDE + kb) * 2;
            LDSM4(BH[nj], sWH + off);
            LDSM4(BL[nj], sWL + off);
        }
#pragma unroll
        for (int mi = 0; mi < 2; mi++) {
#pragma unroll
            for (int nj = 0; nj < 2; nj++) {
                float* cA = acc[mi][nj * 2];
                float* cB = acc[mi][nj * 2 + 1];
                MMA16816(cA, AH[mi][0], AH[mi][1], AH[mi][2], AH[mi][3], BH[nj][0], BH[nj][2]);
                MMA16816(cA, AH[mi][0], AH[mi][1], AH[mi][2], AH[mi][3], BL[nj][0], BL[nj][2]);
                MMA16816(cA, AL[mi][0], AL[mi][1], AL[mi][2], AL[mi][3], BH[nj][0], BH[nj][2]);
                MMA16816(cB, AH[mi][0], AH[mi][1], AH[mi][2], AH[mi][3], BH[nj][1], BH[nj][3]);
                MMA16816(cB, AH[mi][0], AH[mi][1], AH[mi][2], AH[mi][3], BL[nj][1], BL[nj][3]);
                MMA16816(cB, AL[mi][0], AL[mi][1], AL[mi][2], AL[mi][3], BH[nj][1], BH[nj][3]);
            }
        }
    }

    // ---- epilogue ----
    const int g = lane >> 2, tg = lane & 3;
    if (slice < 4) {
        __half* O = Yh + (size_t)slice * NN * HH;
#pragma unroll
        for (int mi = 0; mi < 2; mi++) {
            long ra = row0 + r0 + mi * 16 + g;
            long rb = ra + 8;
#pragma unroll
            for (int j = 0; j < 4; j++) {
                int col = c0 + j * 8 + tg * 2;
                if (ra < NN) *(uint32_t*)(O + ra * 128 + col) = pack_f16(acc[mi][j][0], acc[mi][j][1]);
                if (rb < NN) *(uint32_t*)(O + rb * 128 + col) = pack_f16(acc[mi][j][2], acc[mi][j][3]);
            }
        }
    } else {
#pragma unroll
        for (int mi = 0; mi < 2; mi++) {
            long ra = row0 + r0 + mi * 16 + g;
            long rb = ra + 8;
#pragma unroll
            for (int j = 0; j < 4; j++) {
                int col = c0 + j * 8 + tg * 2;
                float b0 = __ldg(&bias1[col]), b1 = __ldg(&bias1[col + 1]);
                if (ra < NN) {
                    float2 v = { acc[mi][j][0] + b0, acc[mi][j][1] + b1 };
                    *(float2*)(x1 + ra * 128 + col) = v;
                }
                if (rb < NN) {
                    float2 v = { acc[mi][j][2] + b0, acc[mi][j][3] + b1 };
                    *(float2*)(x1 + rb * 128 + col) = v;
                }
            }
        }
    }
}

// ---------------- layer 1 scatter: warp/edge, gather 4 fp16 basis rows of Y ----------------
__global__ void __launch_bounds__(256) scatter1_k(
    const int* __restrict__ src, const int* __restrict__ dst, const int* __restrict__ rel,
    const float* __restrict__ norm, const float* __restrict__ wcomp1,
    const __half* __restrict__ Yh, float* __restrict__ out) {
    int e = (blockIdx.x * 256 + threadIdx.x) >> 5;
    if (e >= EE) return;
    int lane = threadIdx.x & 31;
    int s = __ldg(&src[e]);
    int d = __ldg(&dst[e]);
    int rr = __ldg(&rel[e]);
    float nm = __ldg(&norm[e]);
    float c0 = nm * __ldg(&wcomp1[rr * 4 + 0]);
    float c1 = nm * __ldg(&wcomp1[rr * 4 + 1]);
    float c2 = nm * __ldg(&wcomp1[rr * 4 + 2]);
    float c3 = nm * __ldg(&wcomp1[rr * 4 + 3]);
    const uint2* yp = (const uint2*)Yh + (long)s * 32 + lane;
    const long SS = (long)NN * 32;
    uint2 u0 = __ldg(yp);
    uint2 u1 = __ldg(yp + SS);
    uint2 u2 = __ldg(yp + 2 * SS);
    uint2 u3 = __ldg(yp + 3 * SS);
    float2 a0 = __half22float2(*(const __half2*)&u0.x), b0 = __half22float2(*(const __half2*)&u0.y);
    float2 a1 = __half22float2(*(const __half2*)&u1.x), b1 = __half22float2(*(const __half2*)&u1.y);
    float2 a2 = __half22float2(*(const __half2*)&u2.x), b2 = __half22float2(*(const __half2*)&u2.y);
    float2 a3 = __half22float2(*(const __half2*)&u3.x), b3 = __half22float2(*(const __half2*)&u3.y);
    float4 m;
    m.x = c0 * a0.x + c1 * a1.x + c2 * a2.x + c3 * a3.x;
    m.y = c0 * a0.y + c1 * a1.y + c2 * a2.y + c3 * a3.y;
    m.z = c0 * b0.x + c1 * b1.x + c2 * b2.x + c3 * b3.x;
    m.w = c0 * b0.y + c1 * b1.y + c2 * b2.y + c3 * b3.y;
    redAdd4(out + (long)d * HH + lane * 4, m);
}

// ---------------- layer 2 transform, F=16: grid.y = 5 (4 bases -> Z, slot 4 -> out+bias) ----------------
__global__ void __launch_bounds__(128) transform16(
    const float* __restrict__ X, const float* __restrict__ bases2,
    const float* __restrict__ loop2, const float* __restrict__ bias2,
    float* __restrict__ Z, float* __restrict__ out) {
    __shared__ float ws[128 * 16];
    __shared__ float xs[64][129];
    const int y = blockIdx.y;
    const float* W = (y < 4) ? (bases2 + y * 2048) : loop2;
    float* O = (y < 4) ? (Z + (long)y * NN * CC) : out;
    const int t = threadIdx.x;
    const int col = t & 15, rg = t >> 4;
    const int row0 = blockIdx.x * 64;
    for (int i = t; i < 128 * 16; i += 128) ws[i] = __ldg(&W[i]);
#pragma unroll 4
    for (int i = 0; i < 64; i++) {
        int rr = row0 + i;
        float v = (rr < NN) ? __ldg(&X[(long)rr * 128 + t]) : 0.f;
        xs[i][t] = fmaxf(v, 0.f);   // relu(x1) fused
    }
    __syncthreads();
    const float bv = (y == 4) ? __ldg(&bias2[col]) : 0.f;
    for (int p = 0; p < 8; p++) {
        int rl = p * 8 + rg;
        float a = 0.f;
#pragma unroll 16
        for (int d = 0; d < 128; d++) a = fmaf(xs[rl][d], ws[d * 16 + col], a);
        int rr = row0 + rl;
        if (rr < NN) O[(long)rr * 16 + col] = a + bv;
    }
}

// ---------------- layer 2 scatter: 4 lanes per edge, gather 4 basis rows of Z ----------------
__global__ void __launch_bounds__(256) scatter2_k(
    const int* __restrict__ src, const int* __restrict__ dst, const int* __restrict__ rel,
    const float* __restrict__ norm, const float* __restrict__ wcomp2,
    const float* __restrict__ Z, float* __restrict__ out) {
    int tid = blockIdx.x * 256 + threadIdx.x;
    int e = tid >> 2;
    if (e >= EE) return;
    int q = tid & 3;
    int s = __ldg(&src[e]);
    int d = __ldg(&dst[e]);
    int rr = __ldg(&rel[e]);
    float nm = __ldg(&norm[e]);
    float c0 = nm * __ldg(&wcomp2[rr * 4 + 0]);
    float c1 = nm * __ldg(&wcomp2[rr * 4 + 1]);
    float c2 = nm * __ldg(&wcomp2[rr * 4 + 2]);
    float c3 = nm * __ldg(&wcomp2[rr * 4 + 3]);
    const float4* zp = (const float4*)Z;
    const long SS = (long)NN * 4;
    long base = (long)s * 4 + q;
    float4 v0 = __ldg(zp + base);
    float4 v1 = __ldg(zp + base + SS);
    float4 v2 = __ldg(zp + base + 2 * SS);
    float4 v3 = __ldg(zp + base + 3 * SS);
    float4 m;
    m.x = c0 * v0.x + c1 * v1.x + c2 * v2.x + c3 * v3.x;
    m.y = c0 * v0.y + c1 * v1.y + c2 * v2.y + c3 * v3.y;
    m.z = c0 * v0.z + c1 * v1.z + c2 * v2.z + c3 * v3.z;
    m.w = c0 * v0.w + c1 * v1.w + c2 * v2.w + c3 * v3.w;
    redAdd4(out + (long)d * CC + q * 4, m);
}

// ---------------- launch ----------------
extern "C" void kernel_launch(void* const* d_in, const int* in_sizes, int n_in,
                              void* d_out, int out_size) {
    const int*   src    = (const int*)d_in[0];
    const int*   dst    = (const int*)d_in[1];
    const int*   h      = (const int*)d_in[2];
    const int*   rtab   = (const int*)d_in[3];
    const float* norm   = (const float*)d_in[4];
    const float* bases0 = (const float*)d_in[5];
    const float* wcomp0 = (const float*)d_in[6];
    const float* loop0  = (const float*)d_in[7];
    const float* bias0  = (const float*)d_in[8];
    const float* bases1 = (const float*)d_in[9];
    const float* wcomp1 = (const float*)d_in[10];
    const float* loop1  = (const float*)d_in[11];
    const float* bias1  = (const float*)d_in[12];
    const float* bases2 = (const float*)d_in[13];
    const float* wcomp2 = (const float*)d_in[14];
    const float* loop2  = (const float*)d_in[15];
    const float* bias2  = (const float*)d_in[16];
    float* out = (float*)d_out;

    float *p_x0, *p_x1, *p_z2;
    __half *p_b0h, *p_y1h;
    __nv_bfloat16 *p_whi, *p_wlo;
    cudaGetSymbolAddress((void**)&p_x0, g_x0);
    cudaGetSymbolAddress((void**)&p_x1, g_x1);
    cudaGetSymbolAddress((void**)&p_b0h, g_b0h);
    cudaGetSymbolAddress((void**)&p_y1h, g_y1h);
    cudaGetSymbolAddress((void**)&p_z2, g_z2);
    cudaGetSymbolAddress((void**)&p_whi, g_w1thi);
    cudaGetSymbolAddress((void**)&p_wlo, g_w1tlo);

    static int attr_done = 0;
    if (!attr_done) {
        cudaFuncSetAttribute(mma_t128, cudaFuncAttributeMaxDynamicSharedMemorySize, SMEM_MMA);
        attr_done = 1;
    }

    const int nh_blocks = (NN * HH + 255) / 256;
    const int edge_warp = (EE * 32 + 255) / 256;
    const int row_t64  = (NN + 63) / 64;     // 782

    // prep: W images + fp16 bases0
    prep_w1t<<<(5 * 16384 + 255) / 256, 256>>>(bases1, loop1, p_whi, p_wlo);
    cvt_b0h<<<(BB * NN * 32 + 255) / 256, 256>>>(bases0, p_b0h);

    // ---- layer 0 ----
    init0_k<<<nh_blocks, 256>>>(h, loop0, bias0, p_x0);
    scatter0_k<<<edge_warp, 256>>>(src, dst, h, rtab, norm, p_b0h, wcomp0, p_x0);

    // ---- layer 1: basis products via HMMA (fp16 Y), then basis-gather scatter ----
    mma_t128<<<dim3(row_t64, 5), 256, SMEM_MMA>>>(p_x0, p_whi, p_wlo, p_y1h, p_x1, bias1);
    scatter1_k<<<edge_warp, 256>>>(src, dst, rtab, norm, wcomp1, p_y1h, p_x1);

    // ---- layer 2 ----
    transform16<<<dim3(row_t64, 5), 128>>>(p_x1, bases2, loop2, bias2, p_z2, out);
    scatter2_k<<<(EE * 4 + 255) / 256, 256>>>(src, dst, rtab, norm, wcomp2, p_z2, out);
}

// round 12
// speedup vs baseline: 1.3133x; 1.0532x over previous
#include <cuda_runtime.h>
#include <cuda_bf16.h>
#include <cuda_fp16.h>
#include <cstdint>

#define NN 50000
#define HH 128
#define CC 16
#define RR 8
#define BB 4
#define EE 800000

// ---------------- scratch (device globals; no allocations) ----------------
__device__ float g_x0[(size_t)NN * HH];              // layer0 out (pre-relu)
__device__ float g_x1[(size_t)NN * HH];              // layer1 out (pre-relu)
__device__ __half g_b0h[(size_t)BB * NN * HH];       // fp16 copy of bases0 (51.2 MB, L2-resident)
__device__ __half g_y1h[(size_t)4 * NN * HH];        // layer1 basis products, fp16 (51.2 MB)
__device__ float g_z2[(size_t)4 * NN * CC];          // layer2 basis products Z_b
__device__ __nv_bfloat16 g_w1thi[5 * 128 * 128];     // bf16 hi image (slice 4 = loop1^T used)
__device__ __nv_bfloat16 g_w1tlo[5 * 128 * 128];     // bf16 lo residual
__device__ __half g_w1tf[4 * 128 * 128];             // fp16 single image, slices 0..3 (bases1^T)

// ---------------- helpers ----------------
__device__ __forceinline__ void redAdd4(float* p, float4 v) {
    asm volatile("red.global.add.v4.f32 [%0], {%1, %2, %3, %4};"
                 :: "l"(__cvta_generic_to_global(p)), "f"(v.x), "f"(v.y), "f"(v.z), "f"(v.w)
                 : "memory");
}
__device__ __forceinline__ uint32_t pack_bf16(float a, float b) {
    __nv_bfloat162 t = __floats2bfloat162_rn(a, b);
    return *(uint32_t*)&t;
}
__device__ __forceinline__ uint32_t pack_f16(float a, float b) {
    __half2 t = __floats2half2_rn(a, b);
    return *(uint32_t*)&t;
}
__device__ __forceinline__ uint32_t smem_u32(const void* p) {
    uint32_t a;
    asm("{ .reg .u64 t; cvta.to.shared.u64 t, %1; cvt.u32.u64 %0, t; }" : "=r"(a) : "l"(p));
    return a;
}
#define MMA16816BF(c, a0, a1, a2, a3, b0, b1)                                 \
    asm volatile("mma.sync.aligned.m16n8k16.row.col.f32.bf16.bf16.f32 "       \
                 "{%0,%1,%2,%3}, {%4,%5,%6,%7}, {%8,%9}, {%0,%1,%2,%3};"      \
                 : "+f"((c)[0]), "+f"((c)[1]), "+f"((c)[2]), "+f"((c)[3])     \
                 : "r"(a0), "r"(a1), "r"(a2), "r"(a3), "r"(b0), "r"(b1))
#define MMA16816F(c, a0, a1, a2, a3, b0, b1)                                  \
    asm volatile("mma.sync.aligned.m16n8k16.row.col.f32.f16.f16.f32 "         \
                 "{%0,%1,%2,%3}, {%4,%5,%6,%7}, {%8,%9}, {%0,%1,%2,%3};"      \
                 : "+f"((c)[0]), "+f"((c)[1]), "+f"((c)[2]), "+f"((c)[3])     \
                 : "r"(a0), "r"(a1), "r"(a2), "r"(a3), "r"(b0), "r"(b1))
#define LDSM4(r, addr)                                                        \
    asm volatile("ldmatrix.sync.aligned.m8n8.x4.shared.b16 {%0,%1,%2,%3}, [%4];" \
                 : "=r"((r)[0]), "=r"((r)[1]), "=r"((r)[2]), "=r"((r)[3])     \
                 : "r"(addr))

// smem geometry: 16-bit rows, stride 136 elems (272 B)
#define LSTRIDE 136
// hi/lo kernel (x1): A hi/lo + W hi/lo
#define AH_OFF 0
#define AL_OFF 17408
#define WH_OFF 34816
#define WL_OFF 69632
#define SMEM_X1 104448
// fp16 kernel (Y): single A + single W
#define FA_OFF 0
#define FW_OFF 17408
#define SMEM_F16 52224

// ---------------- prep: weight images ----------------
__global__ void prep_w1t(const float* __restrict__ bases1, const float* __restrict__ loop1,
                         __nv_bfloat16* __restrict__ whi, __nv_bfloat16* __restrict__ wlo,
                         __half* __restrict__ wf) {
    int i = blockIdx.x * 256 + threadIdx.x;
    if (i >= 5 * 16384) return;
    int s = i >> 14;
    int f = (i >> 7) & 127;
    int d = i & 127;
    float v = (s < 4) ? __ldg(&bases1[s * 16384 + d * 128 + f]) : __ldg(&loop1[d * 128 + f]);
    __nv_bfloat16 hi = __float2bfloat16(v);
    __nv_bfloat16 lo = __float2bfloat16(v - __bfloat162float(hi));
    whi[i] = hi;
    wlo[i] = lo;
    if (s < 4) wf[i] = __float2half(v);
}

// ---------------- prep: bases0 fp32 -> fp16 ----------------
__global__ void cvt_b0h(const float* __restrict__ b0, __half* __restrict__ out) {
    int i = blockIdx.x * 256 + threadIdx.x;
    if (i >= BB * NN * 32) return;
    float4 v = __ldg((const float4*)b0 + i);
    __half2 h0 = __floats2half2_rn(v.x, v.y);
    __half2 h1 = __floats2half2_rn(v.z, v.w);
    uint2 u = { *(uint32_t*)&h0, *(uint32_t*)&h1 };
    ((uint2*)out)[i] = u;
}

// ---------------- layer 0 init: x0 = loop0[h] + bias0 ----------------
__global__ void init0_k(const int* __restrict__ h, const float* __restrict__ loop0,
                        const float* __restrict__ bias0, float* __restrict__ out) {
    int i = blockIdx.x * 256 + threadIdx.x;
    if (i >= NN * HH) return;
    int n = i >> 7;
    int f = i & 127;
    int id = __ldg(&h[n]);
    out[i] = __ldg(&loop0[(size_t)id * HH + f]) + __ldg(&bias0[f]);
}

// ---------------- layer 0 scatter: one warp per edge, fp16 basis-gather ----------------
__global__ void __launch_bounds__(256) scatter0_k(
    const int* __restrict__ src, const int* __restrict__ dst, const int* __restrict__ h,
    const int* __restrict__ rel, const float* __restrict__ norm,
    const __half* __restrict__ b0h, const float* __restrict__ wcomp0,
    float* __restrict__ out) {
    int e = (blockIdx.x * 256 + threadIdx.x) >> 5;
    if (e >= EE) return;
    int lane = threadIdx.x & 31;
    int s = __ldg(&src[e]);
    int d = __ldg(&dst[e]);
    int rr = __ldg(&rel[e]);
    float nm = __ldg(&norm[e]);
    int sid = __ldg(&h[s]);
    float c0 = nm * __ldg(&wcomp0[rr * 4 + 0]);
    float c1 = nm * __ldg(&wcomp0[rr * 4 + 1]);
    float c2 = nm * __ldg(&wcomp0[rr * 4 + 2]);
    float c3 = nm * __ldg(&wcomp0[rr * 4 + 3]);
    const uint2* bp = (const uint2*)b0h;
    const long BS = (long)NN * 32;
    long base = (long)sid * 32 + lane;
    uint2 u0 = __ldg(bp + base);
    uint2 u1 = __ldg(bp + base + BS);
    uint2 u2 = __ldg(bp + base + 2 * BS);
    uint2 u3 = __ldg(bp + base + 3 * BS);
    float2 a0 = __half22float2(*(const __half2*)&u0.x), b0 = __half22float2(*(const __half2*)&u0.y);
    float2 a1 = __half22float2(*(const __half2*)&u1.x), b1 = __half22float2(*(const __half2*)&u1.y);
    float2 a2 = __half22float2(*(const __half2*)&u2.x), b2 = __half22float2(*(const __half2*)&u2.y);
    float2 a3 = __half22float2(*(const __half2*)&u3.x), b3 = __half22float2(*(const __half2*)&u3.y);
    float4 m;
    m.x = c0 * a0.x + c1 * a1.x + c2 * a2.x + c3 * a3.x;
    m.y = c0 * a0.y + c1 * a1.y + c2 * a2.y + c3 * a3.y;
    m.z = c0 * b0.x + c1 * b1.x + c2 * b2.x + c3 * b3.x;
    m.w = c0 * b0.y + c1 * b1.y + c2 * b2.y + c3 * b3.y;
    redAdd4(out + (long)d * HH + lane * 4, m);
}

// ---------------- fp16 HMMA transform: Y_b = relu(x0) @ B1_b  (slices 0..3) ----------------
__global__ void __launch_bounds__(256, 3) mma_f16(
    const float* __restrict__ X, const __half* __restrict__ Wf,
    __half* __restrict__ Yh) {
    extern __shared__ char sm[];
    const int tid = threadIdx.x;
    const int w = tid >> 5;
    const int lane = tid & 31;
    const int slice = blockIdx.y;
    const int row0 = blockIdx.x * 64;

    // W fill: warp w -> rows [16w,+16), lane -> 8B chunk
    {
        const uint2* g = (const uint2*)(Wf + slice * 16384);
#pragma unroll
        for (int i = 0; i < 16; i++) {
            int r = w * 16 + i;
            uint2 v = __ldg(g + r * 32 + lane);
            *(uint2*)(sm + FW_OFF + r * (LSTRIDE * 2) + lane * 8) = v;
        }
    }
    // A fill: warp w -> rows [8w,+8), lane -> cols [4*lane,+4), relu + fp16
    {
#pragma unroll
        for (int i = 0; i < 8; i++) {
            int r = w * 8 + i;
            int rg = row0 + r;
            float4 q = (rg < NN) ? __ldg((const float4*)X + (long)rg * 32 + lane)
                                 : make_float4(0.f, 0.f, 0.f, 0.f);
            uint2 u = { pack_f16(fmaxf(q.x, 0.f), fmaxf(q.y, 0.f)),
                        pack_f16(fmaxf(q.z, 0.f), fmaxf(q.w, 0.f)) };
            *(uint2*)(sm + FA_OFF + r * (LSTRIDE * 2) + lane * 8) = u;
        }
    }
    __syncthreads();

    const int wm = w & 1, wn = w >> 1;
    const int r0 = wm * 32, c0 = wn * 32;
    const uint32_t lrow = lane & 15;
    const uint32_t lkh = (lane >> 4) << 3;
    const uint32_t sA = smem_u32(sm + FA_OFF), sW = smem_u32(sm + FW_OFF);

    float acc[2][4][4];
#pragma unroll
    for (int mi = 0; mi < 2; mi++)
#pragma unroll
        for (int j = 0; j < 4; j++)
            acc[mi][j][0] = acc[mi][j][1] = acc[mi][j][2] = acc[mi][j][3] = 0.f;

#pragma unroll
    for (int ks = 0; ks < 8; ks++) {
        const uint32_t kb = ks * 16 + lkh;
        uint32_t A[2][4], B[2][4];
#pragma unroll
        for (int mi = 0; mi < 2; mi++)
            LDSM4(A[mi], sA + ((r0 + mi * 16 + lrow) * LSTRIDE + kb) * 2);
#pragma unroll
        for (int nj = 0; nj < 2; nj++)
            LDSM4(B[nj], sW + ((c0 + nj * 16 + lrow) * LSTRIDE + kb) * 2);
#pragma unroll
        for (int mi = 0; mi < 2; mi++)
#pragma unroll
            for (int nj = 0; nj < 2; nj++) {
                MMA16816F(acc[mi][nj * 2],     A[mi][0], A[mi][1], A[mi][2], A[mi][3], B[nj][0], B[nj][2]);
                MMA16816F(acc[mi][nj * 2 + 1], A[mi][0], A[mi][1], A[mi][2], A[mi][3], B[nj][1], B[nj][3]);
            }
    }

    __half* O = Yh + (size_t)slice * NN * HH;
    const int g = lane >> 2, tg = lane & 3;
#pragma unroll
    for (int mi = 0; mi < 2; mi++) {
        long ra = row0 + r0 + mi * 16 + g;
        long rb = ra + 8;
#pragma unroll
        for (int j = 0; j < 4; j++) {
            int col = c0 + j * 8 + tg * 2;
            if (ra < NN) *(uint32_t*)(O + ra * 128 + col) = pack_f16(acc[mi][j][0], acc[mi][j][1]);
            if (rb < NN) *(uint32_t*)(O + rb * 128 + col) = pack_f16(acc[mi][j][2], acc[mi][j][3]);
        }
    }
}

// ---------------- bf16 hi/lo HMMA: x1 = relu(x0) @ loop1 + bias1 (accurate path) ----------------
__global__ void __launch_bounds__(256, 2) mma_x1(
    const float* __restrict__ X,
    const __nv_bfloat16* __restrict__ Wth, const __nv_bfloat16* __restrict__ Wtl,
    float* __restrict__ x1, const float* __restrict__ bias1) {
    extern __shared__ char sm[];
    const int tid = threadIdx.x;
    const int w = tid >> 5;
    const int lane = tid & 31;
    const int row0 = blockIdx.x * 64;

    {
        const uint2* gh = (const uint2*)(Wth + 4 * 16384);
        const uint2* gl = (const uint2*)(Wtl + 4 * 16384);
#pragma unroll
        for (int i = 0; i < 16; i++) {
            int r = w * 16 + i;
            uint2 vh = __ldg(gh + r * 32 + lane);
            uint2 vl = __ldg(gl + r * 32 + lane);
            *(uint2*)(sm + WH_OFF + r * (LSTRIDE * 2) + lane * 8) = vh;
            *(uint2*)(sm + WL_OFF + r * (LSTRIDE * 2) + lane * 8) = vl;
        }
    }
    {
#pragma unroll
        for (int i = 0; i < 8; i++) {
            int r = w * 8 + i;
            int rg = row0 + r;
            float4 q = (rg < NN) ? __ldg((const float4*)X + (long)rg * 32 + lane)
                                 : make_float4(0.f, 0.f, 0.f, 0.f);
            q.x = fmaxf(q.x, 0.f); q.y = fmaxf(q.y, 0.f);
            q.z = fmaxf(q.z, 0.f); q.w = fmaxf(q.w, 0.f);
            float hx = __bfloat162float(__float2bfloat16(q.x));
            float hy = __bfloat162float(__float2bfloat16(q.y));
            float hz = __bfloat162float(__float2bfloat16(q.z));
            float hw = __bfloat162float(__float2bfloat16(q.w));
            uint2 uh = { pack_bf16(q.x, q.y), pack_bf16(q.z, q.w) };
            uint2 ul = { pack_bf16(q.x - hx, q.y - hy), pack_bf16(q.z - hz, q.w - hw) };
            *(uint2*)(sm + AH_OFF + r * (LSTRIDE * 2) + lane * 8) = uh;
            *(uint2*)(sm + AL_OFF + r * (LSTRIDE * 2) + lane * 8) = ul;
        }
    }
    __syncthreads();

    const int wm = w & 1, wn = w >> 1;
    const int r0 = wm * 32, c0 = wn * 32;
    const uint32_t lrow = lane & 15;
    const uint32_t lkh = (lane >> 4) << 3;
    const uint32_t sAH = smem_u32(sm + AH_OFF), sAL = smem_u32(sm + AL_OFF);
    const uint32_t sWH = smem_u32(sm + WH_OFF), sWL = smem_u32(sm + WL_OFF);

    float acc[2][4][4];
#pragma unroll
    for (int mi = 0; mi < 2; mi++)
#pragma unroll
        for (int j = 0; j < 4; j++)
            acc[mi][j][0] = acc[mi][j][1] = acc[mi][j][2] = acc[mi][j][3] = 0.f;

#pragma unroll
    for (int ks = 0; ks < 8; ks++) {
        const uint32_t kb = ks * 16 + lkh;
        uint32_t AH[2][4], AL[2][4], BH[2][4], BL[2][4];
#pragma unroll
        for (int mi = 0; mi < 2; mi++) {
            uint32_t off = ((r0 + mi * 16 + lrow) * LSTRIDE + kb) * 2;
            LDSM4(AH[mi], sAH + off);
            LDSM4(AL[mi], sAL + off);
        }
#pragma unroll
        for (int nj = 0; nj < 2; nj++) {
            uint32_t off = ((c0 + nj * 16 + lrow) * LSTRIDE + kb) * 2;
            LDSM4(BH[nj], sWH + off);
            LDSM4(BL[nj], sWL + off);
        }
#pragma unroll
        for (int mi = 0; mi < 2; mi++)
#pragma unroll
            for (int nj = 0; nj < 2; nj++) {
                float* cA = acc[mi][nj * 2];
                float* cB = acc[mi][nj * 2 + 1];
                MMA16816BF(cA, AH[mi][0], AH[mi][1], AH[mi][2], AH[mi][3], BH[nj][0], BH[nj][2]);
                MMA16816BF(cA, AH[mi][0], AH[mi][1], AH[mi][2], AH[mi][3], BL[nj][0], BL[nj][2]);
                MMA16816BF(cA, AL[mi][0], AL[mi][1], AL[mi][2], AL[mi][3], BH[nj][0], BH[nj][2]);
                MMA16816BF(cB, AH[mi][0], AH[mi][1], AH[mi][2], AH[mi][3], BH[nj][1], BH[nj][3]);
                MMA16816BF(cB, AH[mi][0], AH[mi][1], AH[mi][2], AH[mi][3], BL[nj][1], BL[nj][3]);
                MMA16816BF(cB, AL[mi][0], AL[mi][1], AL[mi][2], AL[mi][3], BH[nj][1], BH[nj][3]);
            }
    }

    const int g = lane >> 2, tg = lane & 3;
#pragma unroll
    for (int mi = 0; mi < 2; mi++) {
        long ra = row0 + r0 + mi * 16 + g;
        long rb = ra + 8;
#pragma unroll
        for (int j = 0; j < 4; j++) {
            int col = c0 + j * 8 + tg * 2;
            float b0 = __ldg(&bias1[col]), b1 = __ldg(&bias1[col + 1]);
            if (ra < NN) {
                float2 v = { acc[mi][j][0] + b0, acc[mi][j][1] + b1 };
                *(float2*)(x1 + ra * 128 + col) = v;
            }
            if (rb < NN) {
                float2 v = { acc[mi][j][2] + b0, acc[mi][j][3] + b1 };
                *(float2*)(x1 + rb * 128 + col) = v;
            }
        }
    }
}

// ---------------- layer 1 scatter: warp/edge, gather 4 fp16 basis rows of Y ----------------
__global__ void __launch_bounds__(256) scatter1_k(
    const int* __restrict__ src, const int* __restrict__ dst, const int* __restrict__ rel,
    const float* __restrict__ norm, const float* __restrict__ wcomp1,
    const __half* __restrict__ Yh, float* __restrict__ out) {
    int e = (blockIdx.x * 256 + threadIdx.x) >> 5;
    if (e >= EE) return;
    int lane = threadIdx.x & 31;
    int s = __ldg(&src[e]);
    int d = __ldg(&dst[e]);
    int rr = __ldg(&rel[e]);
    float nm = __ldg(&norm[e]);
    float c0 = nm * __ldg(&wcomp1[rr * 4 + 0]);
    float c1 = nm * __ldg(&wcomp1[rr * 4 + 1]);
    float c2 = nm * __ldg(&wcomp1[rr * 4 + 2]);
    float c3 = nm * __ldg(&wcomp1[rr * 4 + 3]);
    const uint2* yp = (const uint2*)Yh + (long)s * 32 + lane;
    const long SS = (long)NN * 32;
    uint2 u0 = __ldg(yp);
    uint2 u1 = __ldg(yp + SS);
    uint2 u2 = __ldg(yp + 2 * SS);
    uint2 u3 = __ldg(yp + 3 * SS);
    float2 a0 = __half22float2(*(const __half2*)&u0.x), b0 = __half22float2(*(const __half2*)&u0.y);
    float2 a1 = __half22float2(*(const __half2*)&u1.x), b1 = __half22float2(*(const __half2*)&u1.y);
    float2 a2 = __half22float2(*(const __half2*)&u2.x), b2 = __half22float2(*(const __half2*)&u2.y);
    float2 a3 = __half22float2(*(const __half2*)&u3.x), b3 = __half22float2(*(const __half2*)&u3.y);
    float4 m;
    m.x = c0 * a0.x + c1 * a1.x + c2 * a2.x + c3 * a3.x;
    m.y = c0 * a0.y + c1 * a1.y + c2 * a2.y + c3 * a3.y;
    m.z = c0 * b0.x + c1 * b1.x + c2 * b2.x + c3 * b3.x;
    m.w = c0 * b0.y + c1 * b1.y + c2 * b2.y + c3 * b3.y;
    redAdd4(out + (long)d * HH + lane * 4, m);
}

// ---------------- layer 2 transform, F=16: grid.y = 5 (4 bases -> Z, slot 4 -> out+bias) ----------------
__global__ void __launch_bounds__(128) transform16(
    const float* __restrict__ X, const float* __restrict__ bases2,
    const float* __restrict__ loop2, const float* __restrict__ bias2,
    float* __restrict__ Z, float* __restrict__ out) {
    __shared__ float ws[128 * 16];
    __shared__ float xs[64][129];
    const int y = blockIdx.y;
    const float* W = (y < 4) ? (bases2 + y * 2048) : loop2;
    float* O = (y < 4) ? (Z + (long)y * NN * CC) : out;
    const int t = threadIdx.x;
    const int col = t & 15, rg = t >> 4;
    const int row0 = blockIdx.x * 64;
    for (int i = t; i < 128 * 16; i += 128) ws[i] = __ldg(&W[i]);
#pragma unroll 4
    for (int i = 0; i < 64; i++) {
        int rr = row0 + i;
        float v = (rr < NN) ? __ldg(&X[(long)rr * 128 + t]) : 0.f;
        xs[i][t] = fmaxf(v, 0.f);   // relu(x1) fused
    }
    __syncthreads();
    const float bv = (y == 4) ? __ldg(&bias2[col]) : 0.f;
    for (int p = 0; p < 8; p++) {
        int rl = p * 8 + rg;
        float a = 0.f;
#pragma unroll 16
        for (int d = 0; d < 128; d++) a = fmaf(xs[rl][d], ws[d * 16 + col], a);
        int rr = row0 + rl;
        if (rr < NN) O[(long)rr * 16 + col] = a + bv;
    }
}

// ---------------- layer 2 scatter: 4 lanes per edge, gather 4 basis rows of Z ----------------
__global__ void __launch_bounds__(256) scatter2_k(
    const int* __restrict__ src, const int* __restrict__ dst, const int* __restrict__ rel,
    const float* __restrict__ norm, const float* __restrict__ wcomp2,
    const float* __restrict__ Z, float* __restrict__ out) {
    int tid = blockIdx.x * 256 + threadIdx.x;
    int e = tid >> 2;
    if (e >= EE) return;
    int q = tid & 3;
    int s = __ldg(&src[e]);
    int d = __ldg(&dst[e]);
    int rr = __ldg(&rel[e]);
    float nm = __ldg(&norm[e]);
    float c0 = nm * __ldg(&wcomp2[rr * 4 + 0]);
    float c1 = nm * __ldg(&wcomp2[rr * 4 + 1]);
    float c2 = nm * __ldg(&wcomp2[rr * 4 + 2]);
    float c3 = nm * __ldg(&wcomp2[rr * 4 + 3]);
    const float4* zp = (const float4*)Z;
    const long SS = (long)NN * 4;
    long base = (long)s * 4 + q;
    float4 v0 = __ldg(zp + base);
    float4 v1 = __ldg(zp + base + SS);
    float4 v2 = __ldg(zp + base + 2 * SS);
    float4 v3 = __ldg(zp + base + 3 * SS);
    float4 m;
    m.x = c0 * v0.x + c1 * v1.x + c2 * v2.x + c3 * v3.x;
    m.y = c0 * v0.y + c1 * v1.y + c2 * v2.y + c3 * v3.y;
    m.z = c0 * v0.z + c1 * v1.z + c2 * v2.z + c3 * v3.z;
    m.w = c0 * v0.w + c1 * v1.w + c2 * v2.w + c3 * v3.w;
    redAdd4(out + (long)d * CC + q * 4, m);
}

// ---------------- launch ----------------
extern "C" void kernel_launch(void* const* d_in, const int* in_sizes, int n_in,
                              void* d_out, int out_size) {
    const int*   src    = (const int*)d_in[0];
    const int*   dst    = (const int*)d_in[1];
    const int*   h      = (const int*)d_in[2];
    const int*   rtab   = (const int*)d_in[3];
    const float* norm   = (const float*)d_in[4];
    const float* bases0 = (const float*)d_in[5];
    const float* wcomp0 = (const float*)d_in[6];
    const float* loop0  = (const float*)d_in[7];
    const float* bias0  = (const float*)d_in[8];
    const float* bases1 = (const float*)d_in[9];
    const float* wcomp1 = (const float*)d_in[10];
    const float* loop1  = (const float*)d_in[11];
    const float* bias1  = (const float*)d_in[12];
    const float* bases2 = (const float*)d_in[13];
    const float* wcomp2 = (const float*)d_in[14];
    const float* loop2  = (const float*)d_in[15];
    const float* bias2  = (const float*)d_in[16];
    float* out = (float*)d_out;

    float *p_x0, *p_x1, *p_z2;
    __half *p_b0h, *p_y1h, *p_wf;
    __nv_bfloat16 *p_whi, *p_wlo;
    cudaGetSymbolAddress((void**)&p_x0, g_x0);
    cudaGetSymbolAddress((void**)&p_x1, g_x1);
    cudaGetSymbolAddress((void**)&p_b0h, g_b0h);
    cudaGetSymbolAddress((void**)&p_y1h, g_y1h);
    cudaGetSymbolAddress((void**)&p_z2, g_z2);
    cudaGetSymbolAddress((void**)&p_whi, g_w1thi);
    cudaGetSymbolAddress((void**)&p_wlo, g_w1tlo);
    cudaGetSymbolAddress((void**)&p_wf, g_w1tf);

    static int attr_done = 0;
    if (!attr_done) {
        cudaFuncSetAttribute(mma_x1, cudaFuncAttributeMaxDynamicSharedMemorySize, SMEM_X1);
        cudaFuncSetAttribute(mma_f16, cudaFuncAttributeMaxDynamicSharedMemorySize, SMEM_F16);
        attr_done = 1;
    }

    const int nh_blocks = (NN * HH + 255) / 256;
    const int edge_warp = (EE * 32 + 255) / 256;
    const int row_t64  = (NN + 63) / 64;     // 782

    // prep
    prep_w1t<<<(5 * 16384 + 255) / 256, 256>>>(bases1, loop1, p_whi, p_wlo, p_wf);
    cvt_b0h<<<(BB * NN * 32 + 255) / 256, 256>>>(bases0, p_b0h);

    // ---- layer 0 ----
    init0_k<<<nh_blocks, 256>>>(h, loop0, bias0, p_x0);
    scatter0_k<<<edge_warp, 256>>>(src, dst, h, rtab, norm, p_b0h, wcomp0, p_x0);

    // ---- layer 1: Y (fp16 single) + x1 (bf16 hi/lo), then basis-gather scatter ----
    mma_f16<<<dim3(row_t64, 4), 256, SMEM_F16>>>(p_x0, p_wf, p_y1h);
    mma_x1<<<row_t64, 256, SMEM_X1>>>(p_x0, p_whi, p_wlo, p_x1, bias1);
    scatter1_k<<<edge_warp, 256>>>(src, dst, rtab, norm, wcomp1, p_y1h, p_x1);

    // ---- layer 2 ----
    transform16<<<dim3(row_t64, 5), 128>>>(p_x1, bases2, loop2, bias2, p_z2, out);
    scatter2_k<<<(EE * 4 + 255) / 256, 256>>>(src, dst, rtab, norm, wcomp2, p_z2, out);
}